// round 16
// baseline (speedup 1.0000x reference)
#include <cuda_runtime.h>
#include <cuda_fp16.h>
#include <cstdint>
#include <math.h>

#define B_ 32768
#define F_ 512
#define H_ 256
#define C_ 100
#define E_ 8

// ---------------- device-global scratch (no allocs allowed) ----------------
__device__ __align__(128) __half g_xH[(size_t)B_ * F_];           // 32 MB fp16
__device__ __align__(128) __half g_w1tH[(size_t)E_ * H_ * F_];    // [e][h][f] 2 MB
__device__ __align__(128) __half g_w2tH[(size_t)E_ * 128 * H_];   // [e][c pad128][h] 0.5 MB
__device__ float g_preds[(size_t)E_ * B_ * C_];
__device__ int   g_top2[B_];
__device__ int   g_counts[E_];

// ---------------- helpers ----------------
__device__ __forceinline__ uint32_t s2u(const void* p) {
    uint32_t a;
    asm("{ .reg .u64 t; cvta.to.shared.u64 t, %1; cvt.u32.u64 %0, t; }" : "=r"(a) : "l"(p));
    return a;
}
__device__ __forceinline__ uint32_t packh2(float f0, float f1) {
    __half h0 = __float2half_rn(f0), h1 = __float2half_rn(f1);
    return (uint32_t)__half_as_ushort(h0) | ((uint32_t)__half_as_ushort(h1) << 16);
}
__device__ __forceinline__ void ldm4(uint32_t* r, uint32_t a) {
    asm volatile("ldmatrix.sync.aligned.m8n8.x4.shared.b16 {%0,%1,%2,%3}, [%4];"
                 : "=r"(r[0]), "=r"(r[1]), "=r"(r[2]), "=r"(r[3]) : "r"(a));
}
__device__ __forceinline__ void mma16816(float* c, const uint32_t* a, const uint32_t* b) {
    asm volatile("mma.sync.aligned.m16n8k16.row.col.f32.f16.f16.f32 "
                 "{%0,%1,%2,%3}, {%4,%5,%6,%7}, {%8,%9}, {%0,%1,%2,%3};"
                 : "+f"(c[0]), "+f"(c[1]), "+f"(c[2]), "+f"(c[3])
                 : "r"(a[0]), "r"(a[1]), "r"(a[2]), "r"(a[3]), "r"(b[0]), "r"(b[1]));
}
__device__ __forceinline__ void cpa(uint32_t dst, const void* src) {
    asm volatile("cp.async.cg.shared.global [%0], [%1], 16;" :: "r"(dst), "l"(src));
}

// ---------------- prep kernels ----------------
__global__ __launch_bounds__(256) void prep_x(const float* __restrict__ x) {
    size_t gid = (size_t)blockIdx.x * 256 + threadIdx.x;
    const float4* s = (const float4*)(x + gid * 8);
    float4 f0 = s[0], f1 = s[1];
    uint4 hi;
    hi.x = packh2(f0.x, f0.y); hi.y = packh2(f0.z, f0.w);
    hi.z = packh2(f1.x, f1.y); hi.w = packh2(f1.z, f1.w);
    *(uint4*)(g_xH + gid * 8) = hi;
}

__global__ __launch_bounds__(256) void prep_w1t(const float* __restrict__ W1) {
    __shared__ float tile[64][65];
    const int tid = threadIdx.x, b = blockIdx.x;
    const int e = b >> 5, t = b & 31;
    const int fo = (t >> 2) * 64, ho = (t & 3) * 64;
    {
        int r = tid >> 2, c = (tid & 3) * 16;
        const float* src = W1 + ((size_t)e * F_ + fo + r) * H_ + ho + c;
#pragma unroll
        for (int q = 0; q < 4; q++) {
            float4 v = *(const float4*)(src + q * 4);
            tile[r][c + q * 4 + 0] = v.x;
            tile[r][c + q * 4 + 1] = v.y;
            tile[r][c + q * 4 + 2] = v.z;
            tile[r][c + q * 4 + 3] = v.w;
        }
    }
    __syncthreads();
    {
        int hr = tid >> 2, c = (tid & 3) * 16;
        uint4 o0, o1;
        o0.x = packh2(tile[c + 0][hr],  tile[c + 1][hr]);
        o0.y = packh2(tile[c + 2][hr],  tile[c + 3][hr]);
        o0.z = packh2(tile[c + 4][hr],  tile[c + 5][hr]);
        o0.w = packh2(tile[c + 6][hr],  tile[c + 7][hr]);
        o1.x = packh2(tile[c + 8][hr],  tile[c + 9][hr]);
        o1.y = packh2(tile[c + 10][hr], tile[c + 11][hr]);
        o1.z = packh2(tile[c + 12][hr], tile[c + 13][hr]);
        o1.w = packh2(tile[c + 14][hr], tile[c + 15][hr]);
        __half* dst = g_w1tH + ((size_t)e * H_ + ho + hr) * F_ + fo + c;
        *(uint4*)dst = o0;
        *(uint4*)(dst + 8) = o1;
    }
}

__global__ __launch_bounds__(256) void prep_w2(const float* __restrict__ W2) {
    int gid = blockIdx.x * 256 + threadIdx.x;             // 8*128*32
    int e = gid >> 12, c = (gid >> 5) & 127, h8 = gid & 31;
    float f[8];
#pragma unroll
    for (int j = 0; j < 8; j++)
        f[j] = (c < C_) ? W2[((size_t)e * H_ + h8 * 8 + j) * C_ + c] : 0.f;
    uint4 hi;
    hi.x = packh2(f[0], f[1]); hi.y = packh2(f[2], f[3]);
    hi.z = packh2(f[4], f[5]); hi.w = packh2(f[6], f[7]);
    *(uint4*)(g_w2tH + ((size_t)e * 128 + c) * H_ + h8 * 8) = hi;
}

__global__ __launch_bounds__(256) void zero_combined(float* __restrict__ combined) {
    size_t gid = (size_t)blockIdx.x * 256 + threadIdx.x;  // x16 floats
    float4 z = make_float4(0.f, 0.f, 0.f, 0.f);
    float4* p = (float4*)(combined + gid * 16);
    p[0] = z; p[1] = z; p[2] = z; p[3] = z;
}

// ---------------- fused expert kernel (M=64 CTA, 2 CTAs/SM) ----------------
// GEMM1 (kc=64, XOR swizzle) -> epilogue1 -> GEMM2 -> epilogue2 writes preds AND
// an SMEM preds tile -> per-warp softmax + atomicAdd 0.5*softmax into combined
// for rows routed to this expert (g_top2). Two FP atomic adds per element are
// commutative -> bit-deterministic.
#define STG  40960                 // one stage: A 64x128B (8KB) + B 256x128B (32KB)
#define HSTR 528                   // h / W2 row stride bytes
#define HHI  81920                 // h tile base (after 2 stages; W2 reuses staging)
#define PSTR 112                   // preds smem tile row stride (floats)
#define SMEM_TOT 115712            // 81920 + 64*528 (preds tile 64*112*4=28672 <= 33792)

__global__ void __launch_bounds__(256, 2)
fused_moe(const float* __restrict__ b1g, const float* __restrict__ b2g,
          float* __restrict__ preds_arg, float* __restrict__ combined) {
    extern __shared__ __align__(128) unsigned char sm[];
    const uint32_t sb = s2u(sm);
    const int tid = threadIdx.x;
    const int m0 = blockIdx.x * 64, e = blockIdx.y;
    float* preds = preds_arg ? preds_arg : g_preds;

    const __half* Asrc = g_xH + (size_t)m0 * F_;
    const __half* Bsrc = g_w1tH + (size_t)e * H_ * F_;
    const __half* Wsrc = g_w2tH + (size_t)e * 128 * H_;

    const int l = tid & 31, warp = tid >> 5, wr = warp & 1, wc = warp >> 1;
    const uint32_t xr = l & 7;

    auto load1 = [&](int buf, int k0) {
#pragma unroll
        for (int j = 0; j < 2; j++) {   // A: 64 rows x 8 chunks
            int idx = tid + j * 256;
            int r = idx >> 3, c = idx & 7;
            cpa(sb + buf * STG + r * 128 + ((c ^ (r & 7)) << 4),
                Asrc + (size_t)r * F_ + k0 + c * 8);
        }
#pragma unroll
        for (int j = 0; j < 8; j++) {   // B: 256 rows x 8 chunks
            int idx = tid + j * 256;
            int r = idx >> 3, c = idx & 7;
            cpa(sb + buf * STG + 8192 + r * 128 + ((c ^ (r & 7)) << 4),
                Bsrc + (size_t)r * F_ + k0 + c * 8);
        }
        asm volatile("cp.async.commit_group;" ::: "memory");
    };

    // ---------------- GEMM1 ----------------
    const uint32_t aRow0 = (uint32_t)(wr * 32 + (l & 15)) * 128;
    const uint32_t bRow  = (uint32_t)(wc * 64 + ((l >> 4) << 3) + (l & 7)) * 128;

    float acc[2][8][4];
#pragma unroll
    for (int i = 0; i < 2; i++)
#pragma unroll
        for (int j = 0; j < 8; j++)
#pragma unroll
            for (int q = 0; q < 4; q++) acc[i][j][q] = 0.f;

    load1(0, 0);
    const int NS1 = F_ / 64;   // 8
    int buf = 0;
    for (int s = 0; s < NS1; s++) {
        asm volatile("cp.async.wait_group 0;" ::: "memory");
        __syncthreads();
        if (s + 1 < NS1) load1(buf ^ 1, (s + 1) * 64);
        const uint32_t base = sb + buf * STG;
#pragma unroll
        for (int h = 0; h < 4; h++) {
            uint32_t a4[2][4];
#pragma unroll
            for (int mi = 0; mi < 2; mi++)
                ldm4(a4[mi], base + aRow0 + mi * 2048 + ((((l >> 4) + 2 * h) ^ xr) << 4));
#pragma unroll
            for (int ni = 0; ni < 4; ni++) {
                uint32_t b4[4];
                ldm4(b4, base + 8192 + bRow + ni * 2048 + (((((l >> 3) & 1) + 2 * h) ^ xr) << 4));
#pragma unroll
                for (int mi = 0; mi < 2; mi++)
#pragma unroll
                    for (int sj = 0; sj < 2; sj++)
                        mma16816(acc[mi][ni * 2 + sj], a4[mi], b4 + 2 * sj);
            }
        }
        buf ^= 1;
    }

    __syncthreads();
    {   // load whole W2 into staging region, stride 528
#pragma unroll
        for (int j = 0; j < 16; j++) {
            int idx = tid + j * 256;
            int r = idx >> 5, kc16 = idx & 31;
            cpa(sb + r * HSTR + kc16 * 16, Wsrc + (size_t)r * H_ + kc16 * 8);
        }
        asm volatile("cp.async.commit_group;" ::: "memory");
    }

    // ---------------- epilogue 1: relu(+b1) -> fp16 h in SMEM ----------------
    {
        const float* bs1 = b1g + e * H_;
#pragma unroll
        for (int mi = 0; mi < 2; mi++) {
            int rB = wr * 32 + mi * 16 + (l >> 2);
#pragma unroll
            for (int ni = 0; ni < 8; ni++) {
                int n = wc * 64 + ni * 8 + (l & 3) * 2;
#pragma unroll
                for (int hf = 0; hf < 2; hf++) {
                    int r = rB + hf * 8;
                    float v0 = fmaxf(acc[mi][ni][hf * 2 + 0] + bs1[n], 0.f);
                    float v1 = fmaxf(acc[mi][ni][hf * 2 + 1] + bs1[n + 1], 0.f);
                    *(uint32_t*)(sm + HHI + r * HSTR + n * 2) = packh2(v0, v1);
                }
            }
        }
    }
    asm volatile("cp.async.wait_group 0;" ::: "memory");
    __syncthreads();

    // ---------------- GEMM2: h @ W2^T ----------------
    const uint32_t a2Off = (uint32_t)(wr * 32 + (l & 15)) * HSTR + (l >> 4) * 16;
    const uint32_t b2Off = (uint32_t)(wc * 32 + ((l >> 4) << 3) + (l & 7)) * HSTR + ((l >> 3) & 1) * 16;

    float acc2[2][4][4];
#pragma unroll
    for (int i = 0; i < 2; i++)
#pragma unroll
        for (int j = 0; j < 4; j++)
#pragma unroll
            for (int q = 0; q < 4; q++) acc2[i][j][q] = 0.f;

    const int nimax = (wc == 3) ? 1 : 2;
#pragma unroll
    for (int s = 0; s < H_ / 32; s++) {
#pragma unroll
        for (int h = 0; h < 2; h++) {
            uint32_t ah[2][4];
            ldm4(ah[0], sb + HHI + a2Off + s * 64 + h * 32);
            ldm4(ah[1], sb + HHI + a2Off + 16 * HSTR + s * 64 + h * 32);
#pragma unroll
            for (int ni = 0; ni < 2; ni++) {
                if (ni >= nimax) break;
                uint32_t b4[4];
                ldm4(b4, sb + b2Off + ni * 16 * HSTR + s * 64 + h * 32);
#pragma unroll
                for (int mi = 0; mi < 2; mi++)
#pragma unroll
                    for (int sj = 0; sj < 2; sj++)
                        mma16816(acc2[mi][ni * 2 + sj], ah[mi], b4 + 2 * sj);
            }
        }
    }

    // ---------------- epilogue 2: + b2 -> preds (gmem) + preds tile (smem) ----------------
    __syncthreads();                        // all warps done reading h region
    float* sp = (float*)(sm + HHI);         // 64 x PSTR floats preds tile
    {
        const float* bs2 = b2g + e * C_;
#pragma unroll
        for (int mi = 0; mi < 2; mi++) {
            int rB = wr * 32 + mi * 16 + (l >> 2);
#pragma unroll
            for (int ni = 0; ni < 4; ni++) {
                int n = wc * 32 + ni * 8 + (l & 3) * 2;
#pragma unroll
                for (int hf = 0; hf < 2; hf++) {
                    int r = rB + hf * 8;
                    int m = m0 + r;
                    size_t o = ((size_t)e * B_ + m) * C_;
                    float v0 = acc2[mi][ni][hf * 2 + 0];
                    float v1 = acc2[mi][ni][hf * 2 + 1];
                    if (n < C_)     { float t = v0 + bs2[n];     preds[o + n]     = t; sp[r * PSTR + n]     = t; }
                    if (n + 1 < C_) { float t = v1 + bs2[n + 1]; preds[o + n + 1] = t; sp[r * PSTR + n + 1] = t; }
                }
            }
        }
    }
    __syncthreads();                        // publish preds tile

    // ---------------- fused combine: rows routed to e ----------------
    {
#pragma unroll 1
        for (int rr = 0; rr < 8; rr++) {
            int r = warp * 8 + rr, m = m0 + r;
            int pk = g_top2[m];
            if ((pk & 0xFF) != e && ((pk >> 8) & 0xFF) != e) continue;
            const float* pr = sp + r * PSTR;
            float v[4];
            float mx = -3.4e38f;
#pragma unroll
            for (int i = 0; i < 4; i++) {
                int c = l + i * 32;
                v[i] = (c < C_) ? pr[c] : -3.4e38f;
                mx = fmaxf(mx, v[i]);
            }
#pragma unroll
            for (int off = 16; off; off >>= 1)
                mx = fmaxf(mx, __shfl_xor_sync(0xffffffffu, mx, off));
            float s = 0.f;
#pragma unroll
            for (int i = 0; i < 4; i++) {
                int c = l + i * 32;
                v[i] = (c < C_) ? expf(v[i] - mx) : 0.f;
                s += v[i];
            }
#pragma unroll
            for (int off = 16; off; off >>= 1)
                s += __shfl_xor_sync(0xffffffffu, s, off);
            float sc = 0.5f / s;
            float* outr = combined + (size_t)m * C_;
#pragma unroll
            for (int i = 0; i < 4; i++) {
                int c = l + i * 32;
                if (c < C_) atomicAdd(&outr[c], v[i] * sc);
            }
        }
    }
}

// ---------------- gating (standalone, proven) ----------------
__global__ __launch_bounds__(256) void gate_kernel(const float* __restrict__ x,
                                                   const float* __restrict__ Wg) {
    __shared__ float wgs[F_ * 9];
    __shared__ int cnt[E_];
    const int tid = threadIdx.x;
    if (tid < E_) cnt[tid] = 0;
    for (int i = tid; i < F_ * E_; i += 256) {
        int f = i >> 3, e = i & 7;
        wgs[f * 9 + e] = Wg[i];
    }
    __syncthreads();
    const int warp = tid >> 5, lane = tid & 31;
    const int row = blockIdx.x * 8 + warp;
    const float* xr = x + (size_t)row * F_;
    float acc[E_];
#pragma unroll
    for (int e = 0; e < E_; e++) acc[e] = 0.f;
#pragma unroll
    for (int i = 0; i < F_ / 32; i++) {
        int f = i * 32 + lane;
        float xv = xr[f];
#pragma unroll
        for (int e = 0; e < E_; e++) acc[e] += xv * wgs[f * 9 + e];
    }
#pragma unroll
    for (int off = 16; off; off >>= 1)
#pragma unroll
        for (int e = 0; e < E_; e++) acc[e] += __shfl_xor_sync(0xffffffffu, acc[e], off);
    if (lane == 0) {
        int i1 = 0;
#pragma unroll
        for (int e = 1; e < E_; e++) if (acc[e] > acc[i1]) i1 = e;
        int i2 = (i1 == 0) ? 1 : 0;
#pragma unroll
        for (int e = 0; e < E_; e++) if (e != i1 && acc[e] > acc[i2]) i2 = e;
        g_top2[row] = i1 | (i2 << 8);
        atomicAdd(&cnt[i1], 1);
        atomicAdd(&cnt[i2], 1);
    }
    __syncthreads();
    if (tid < E_ && cnt[tid]) atomicAdd(&g_counts[tid], cnt[tid]);
}

__global__ void zero_counts_kernel() { if (threadIdx.x < E_) g_counts[threadIdx.x] = 0; }
__global__ void write_counts_kernel(float* __restrict__ dst) {
    if (threadIdx.x < E_) dst[threadIdx.x] = (float)g_counts[threadIdx.x];
}

// ---------------------------------------------------------------------------
extern "C" void kernel_launch(void* const* d_in, const int* in_sizes, int n_in,
                              void* d_out, int out_size) {
    const float* x  = (const float*)d_in[0];
    const float* W1 = (const float*)d_in[1];
    const float* b1 = (const float*)d_in[2];
    const float* W2 = (const float*)d_in[3];
    const float* b2 = (const float*)d_in[4];
    const float* Wg = (const float*)d_in[5];
    float* out = (float*)d_out;

    const size_t n_combined = (size_t)B_ * C_;
    const size_t n_preds    = (size_t)E_ * B_ * C_;
    const bool has_preds  = (size_t)out_size >= n_combined + n_preds;
    const bool has_counts = (size_t)out_size >= n_combined + n_preds + E_;
    float* combined  = out;
    float* preds_out = has_preds ? out + n_combined : nullptr;

    zero_counts_kernel<<<1, 32>>>();
    zero_combined<<<(B_ * C_ / 16) / 256, 256>>>(combined);
    prep_w1t<<<256, 256>>>(W1);
    prep_w2<<<128, 256>>>(W2);
    prep_x<<<8192, 256>>>(x);
    gate_kernel<<<B_ / 8, 256>>>(x, Wg);

    cudaFuncSetAttribute(fused_moe, cudaFuncAttributeMaxDynamicSharedMemorySize, SMEM_TOT);
    fused_moe<<<dim3(B_ / 64, E_), 256, SMEM_TOT>>>(b1, b2, preds_out, combined);

    if (has_counts) write_counts_kernel<<<1, 32>>>(out + n_combined + n_preds);
}

// round 17
// speedup vs baseline: 1.0793x; 1.0793x over previous
#include <cuda_runtime.h>
#include <cuda_fp16.h>
#include <cstdint>
#include <math.h>

#define B_ 32768
#define F_ 512
#define H_ 256
#define C_ 100
#define E_ 8

// ---------------- device-global scratch (no allocs allowed) ----------------
__device__ __align__(128) __half g_xH[(size_t)B_ * F_];           // 32 MB fp16
__device__ __align__(128) __half g_w1tH[(size_t)E_ * H_ * F_];    // [e][h][f] 2 MB
__device__ __align__(128) __half g_w2tH[(size_t)E_ * 128 * H_];   // [e][c pad128][h] 0.5 MB
__device__ float g_preds[(size_t)E_ * B_ * C_];
__device__ int   g_top2[B_];
__device__ int   g_counts[E_];

// ---------------- helpers ----------------
__device__ __forceinline__ uint32_t s2u(const void* p) {
    uint32_t a;
    asm("{ .reg .u64 t; cvta.to.shared.u64 t, %1; cvt.u32.u64 %0, t; }" : "=r"(a) : "l"(p));
    return a;
}
__device__ __forceinline__ uint32_t packh2(float f0, float f1) {
    __half h0 = __float2half_rn(f0), h1 = __float2half_rn(f1);
    return (uint32_t)__half_as_ushort(h0) | ((uint32_t)__half_as_ushort(h1) << 16);
}
__device__ __forceinline__ void ldm4(uint32_t* r, uint32_t a) {
    asm volatile("ldmatrix.sync.aligned.m8n8.x4.shared.b16 {%0,%1,%2,%3}, [%4];"
                 : "=r"(r[0]), "=r"(r[1]), "=r"(r[2]), "=r"(r[3]) : "r"(a));
}
__device__ __forceinline__ void mma16816(float* c, const uint32_t* a, const uint32_t* b) {
    asm volatile("mma.sync.aligned.m16n8k16.row.col.f32.f16.f16.f32 "
                 "{%0,%1,%2,%3}, {%4,%5,%6,%7}, {%8,%9}, {%0,%1,%2,%3};"
                 : "+f"(c[0]), "+f"(c[1]), "+f"(c[2]), "+f"(c[3])
                 : "r"(a[0]), "r"(a[1]), "r"(a[2]), "r"(a[3]), "r"(b[0]), "r"(b[1]));
}
__device__ __forceinline__ void cpa(uint32_t dst, const void* src) {
    asm volatile("cp.async.cg.shared.global [%0], [%1], 16;" :: "r"(dst), "l"(src));
}

// ---------------- prep kernels (round-15 proven) ----------------
__global__ __launch_bounds__(256) void prep_x(const float* __restrict__ x) {
    size_t gid = (size_t)blockIdx.x * 256 + threadIdx.x;
    const float4* s = (const float4*)(x + gid * 8);
    float4 f0 = s[0], f1 = s[1];
    uint4 hi;
    hi.x = packh2(f0.x, f0.y); hi.y = packh2(f0.z, f0.w);
    hi.z = packh2(f1.x, f1.y); hi.w = packh2(f1.z, f1.w);
    *(uint4*)(g_xH + gid * 8) = hi;
}

__global__ __launch_bounds__(256) void prep_w1t(const float* __restrict__ W1) {
    __shared__ float tile[64][65];
    const int tid = threadIdx.x, b = blockIdx.x;
    const int e = b >> 5, t = b & 31;
    const int fo = (t >> 2) * 64, ho = (t & 3) * 64;
    {
        int r = tid >> 2, c = (tid & 3) * 16;
        const float* src = W1 + ((size_t)e * F_ + fo + r) * H_ + ho + c;
#pragma unroll
        for (int q = 0; q < 4; q++) {
            float4 v = *(const float4*)(src + q * 4);
            tile[r][c + q * 4 + 0] = v.x;
            tile[r][c + q * 4 + 1] = v.y;
            tile[r][c + q * 4 + 2] = v.z;
            tile[r][c + q * 4 + 3] = v.w;
        }
    }
    __syncthreads();
    {
        int hr = tid >> 2, c = (tid & 3) * 16;
        uint4 o0, o1;
        o0.x = packh2(tile[c + 0][hr],  tile[c + 1][hr]);
        o0.y = packh2(tile[c + 2][hr],  tile[c + 3][hr]);
        o0.z = packh2(tile[c + 4][hr],  tile[c + 5][hr]);
        o0.w = packh2(tile[c + 6][hr],  tile[c + 7][hr]);
        o1.x = packh2(tile[c + 8][hr],  tile[c + 9][hr]);
        o1.y = packh2(tile[c + 10][hr], tile[c + 11][hr]);
        o1.z = packh2(tile[c + 12][hr], tile[c + 13][hr]);
        o1.w = packh2(tile[c + 14][hr], tile[c + 15][hr]);
        __half* dst = g_w1tH + ((size_t)e * H_ + ho + hr) * F_ + fo + c;
        *(uint4*)dst = o0;
        *(uint4*)(dst + 8) = o1;
    }
}

__global__ __launch_bounds__(256) void prep_w2(const float* __restrict__ W2) {
    int gid = blockIdx.x * 256 + threadIdx.x;             // 8*128*32
    int e = gid >> 12, c = (gid >> 5) & 127, h8 = gid & 31;
    float f[8];
#pragma unroll
    for (int j = 0; j < 8; j++)
        f[j] = (c < C_) ? W2[((size_t)e * H_ + h8 * 8 + j) * C_ + c] : 0.f;
    uint4 hi;
    hi.x = packh2(f[0], f[1]); hi.y = packh2(f[2], f[3]);
    hi.z = packh2(f[4], f[5]); hi.w = packh2(f[6], f[7]);
    *(uint4*)(g_w2tH + ((size_t)e * 128 + c) * H_ + h8 * 8) = hi;
}

// ---------------- fused expert kernel: 4 warps, warp tile m64n64 ----------------
// CTA = 64 rows x 256 n, 128 threads. GEMM1 warp w: m[0,64) x n[w*64,(w+1)*64).
// kc=64 stages, XOR swizzle. GEMM2 warp tile m64n32. 2 CTAs/SM.
#define STG  40960                 // one stage: A 64x128B (8KB) + B 256x128B (32KB)
#define HSTR 528                   // h / W2 row stride bytes
#define HHI  81920                 // h tile base (after 2 stages; W2 reuses staging)
#define SMEM_TOT 115712            // 81920 + 64*528

__global__ void __launch_bounds__(128, 2)
fused_moe(const float* __restrict__ b1g, const float* __restrict__ b2g,
          float* __restrict__ preds_arg) {
    extern __shared__ __align__(128) unsigned char sm[];
    const uint32_t sb = s2u(sm);
    const int tid = threadIdx.x;
    const int m0 = blockIdx.x * 64, e = blockIdx.y;
    float* preds = preds_arg ? preds_arg : g_preds;

    const __half* Asrc = g_xH + (size_t)m0 * F_;
    const __half* Bsrc = g_w1tH + (size_t)e * H_ * F_;
    const __half* Wsrc = g_w2tH + (size_t)e * 128 * H_;

    const int l = tid & 31, w = tid >> 5;       // 4 warps
    const uint32_t xr = l & 7;

    auto load1 = [&](int buf, int k0) {
#pragma unroll
        for (int j = 0; j < 4; j++) {   // A: 512 chunks
            int idx = tid + j * 128;
            int r = idx >> 3, c = idx & 7;
            cpa(sb + buf * STG + r * 128 + ((c ^ (r & 7)) << 4),
                Asrc + (size_t)r * F_ + k0 + c * 8);
        }
#pragma unroll
        for (int j = 0; j < 16; j++) {  // B: 2048 chunks
            int idx = tid + j * 128;
            int r = idx >> 3, c = idx & 7;
            cpa(sb + buf * STG + 8192 + r * 128 + ((c ^ (r & 7)) << 4),
                Bsrc + (size_t)r * F_ + k0 + c * 8);
        }
        asm volatile("cp.async.commit_group;" ::: "memory");
    };

    // ---------------- GEMM1: warp tile m64n64 ----------------
    const uint32_t aRowL = (uint32_t)(l & 15) * 128;                       // + mi*2048
    const uint32_t bRow  = (uint32_t)(w * 64 + ((l >> 4) << 3) + (l & 7)) * 128;  // + ni*2048

    float acc[4][8][4];
#pragma unroll
    for (int i = 0; i < 4; i++)
#pragma unroll
        for (int j = 0; j < 8; j++)
#pragma unroll
            for (int q = 0; q < 4; q++) acc[i][j][q] = 0.f;

    load1(0, 0);
    const int NS1 = F_ / 64;   // 8
    int buf = 0;
    for (int s = 0; s < NS1; s++) {
        asm volatile("cp.async.wait_group 0;" ::: "memory");
        __syncthreads();
        if (s + 1 < NS1) load1(buf ^ 1, (s + 1) * 64);
        const uint32_t base = sb + buf * STG;
#pragma unroll
        for (int h = 0; h < 4; h++) {
            uint32_t a4[4][4];
#pragma unroll
            for (int mi = 0; mi < 4; mi++)
                ldm4(a4[mi], base + aRowL + mi * 2048 + ((((l >> 4) + 2 * h) ^ xr) << 4));
#pragma unroll
            for (int ni = 0; ni < 4; ni++) {
                uint32_t b4[4];
                ldm4(b4, base + 8192 + bRow + ni * 2048 + (((((l >> 3) & 1) + 2 * h) ^ xr) << 4));
#pragma unroll
                for (int mi = 0; mi < 4; mi++)
#pragma unroll
                    for (int sj = 0; sj < 2; sj++)
                        mma16816(acc[mi][ni * 2 + sj], a4[mi], b4 + 2 * sj);
            }
        }
        buf ^= 1;
    }

    __syncthreads();
    {   // load whole W2 [128 rows][512B] into staging region, stride 528
#pragma unroll
        for (int j = 0; j < 32; j++) {
            int idx = tid + j * 128;             // 4096 16B-chunks
            int r = idx >> 5, kc16 = idx & 31;
            cpa(sb + r * HSTR + kc16 * 16, Wsrc + (size_t)r * H_ + kc16 * 8);
        }
        asm volatile("cp.async.commit_group;" ::: "memory");
    }

    // ---------------- epilogue 1: relu(+b1) -> fp16 h in SMEM ----------------
    {
        const float* bs1 = b1g + e * H_;
#pragma unroll
        for (int mi = 0; mi < 4; mi++) {
            int rB = mi * 16 + (l >> 2);
#pragma unroll
            for (int ni = 0; ni < 8; ni++) {
                int n = w * 64 + ni * 8 + (l & 3) * 2;
#pragma unroll
                for (int hf = 0; hf < 2; hf++) {
                    int r = rB + hf * 8;
                    float v0 = fmaxf(acc[mi][ni][hf * 2 + 0] + bs1[n], 0.f);
                    float v1 = fmaxf(acc[mi][ni][hf * 2 + 1] + bs1[n + 1], 0.f);
                    *(uint32_t*)(sm + HHI + r * HSTR + n * 2) = packh2(v0, v1);
                }
            }
        }
    }
    asm volatile("cp.async.wait_group 0;" ::: "memory");
    __syncthreads();   // publishes h and W2

    // ---------------- GEMM2: h @ W2^T, warp tile m64n32, sync-free ----------------
    // warp w covers n = w*32 + ni*16 + sj*8; w==3,ni==1 -> n in [112,128) >= C_: skip.
    const uint32_t a2Off = (uint32_t)(l & 15) * HSTR + (l >> 4) * 16;   // + mi*16*HSTR
    const uint32_t b2Off = (uint32_t)(w * 32 + ((l >> 4) << 3) + (l & 7)) * HSTR + ((l >> 3) & 1) * 16;

    float acc2[4][4][4];
#pragma unroll
    for (int i = 0; i < 4; i++)
#pragma unroll
        for (int j = 0; j < 4; j++)
#pragma unroll
            for (int q = 0; q < 4; q++) acc2[i][j][q] = 0.f;

    const int nimax = (w == 3) ? 1 : 2;
#pragma unroll
    for (int s = 0; s < H_ / 32; s++) {
#pragma unroll
        for (int h = 0; h < 2; h++) {
            uint32_t ah[4][4];
#pragma unroll
            for (int mi = 0; mi < 4; mi++)
                ldm4(ah[mi], sb + HHI + a2Off + mi * 16 * HSTR + s * 64 + h * 32);
#pragma unroll
            for (int ni = 0; ni < 2; ni++) {
                if (ni >= nimax) break;
                uint32_t b4[4];
                ldm4(b4, sb + b2Off + ni * 16 * HSTR + s * 64 + h * 32);
#pragma unroll
                for (int mi = 0; mi < 4; mi++)
#pragma unroll
                    for (int sj = 0; sj < 2; sj++)
                        mma16816(acc2[mi][ni * 2 + sj], ah[mi], b4 + 2 * sj);
            }
        }
    }

    // ---------------- epilogue 2: + b2 -> preds ----------------
    {
        const float* bs2 = b2g + e * C_;
#pragma unroll
        for (int mi = 0; mi < 4; mi++) {
            int mB = m0 + mi * 16 + (l >> 2);
#pragma unroll
            for (int g = 0; g < 4; g++) {
                int n = w * 32 + g * 8 + (l & 3) * 2;
#pragma unroll
                for (int hf = 0; hf < 2; hf++) {
                    int m = mB + hf * 8;
                    size_t o = ((size_t)e * B_ + m) * C_;
                    if (n < C_)     preds[o + n]     = acc2[mi][g][hf * 2 + 0] + bs2[n];
                    if (n + 1 < C_) preds[o + n + 1] = acc2[mi][g][hf * 2 + 1] + bs2[n + 1];
                }
            }
        }
    }
}

// ---------------- gating (standalone, proven) ----------------
__global__ __launch_bounds__(256) void gate_kernel(const float* __restrict__ x,
                                                   const float* __restrict__ Wg) {
    __shared__ float wgs[F_ * 9];
    __shared__ int cnt[E_];
    const int tid = threadIdx.x;
    if (tid < E_) cnt[tid] = 0;
    for (int i = tid; i < F_ * E_; i += 256) {
        int f = i >> 3, e = i & 7;
        wgs[f * 9 + e] = Wg[i];
    }
    __syncthreads();
    const int warp = tid >> 5, lane = tid & 31;
    const int row = blockIdx.x * 8 + warp;
    const float* xr = x + (size_t)row * F_;
    float acc[E_];
#pragma unroll
    for (int e = 0; e < E_; e++) acc[e] = 0.f;
#pragma unroll
    for (int i = 0; i < F_ / 32; i++) {
        int f = i * 32 + lane;
        float xv = xr[f];
#pragma unroll
        for (int e = 0; e < E_; e++) acc[e] += xv * wgs[f * 9 + e];
    }
#pragma unroll
    for (int off = 16; off; off >>= 1)
#pragma unroll
        for (int e = 0; e < E_; e++) acc[e] += __shfl_xor_sync(0xffffffffu, acc[e], off);
    if (lane == 0) {
        int i1 = 0;
#pragma unroll
        for (int e = 1; e < E_; e++) if (acc[e] > acc[i1]) i1 = e;
        int i2 = (i1 == 0) ? 1 : 0;
#pragma unroll
        for (int e = 0; e < E_; e++) if (e != i1 && acc[e] > acc[i2]) i2 = e;
        g_top2[row] = i1 | (i2 << 8);
        atomicAdd(&cnt[i1], 1);
        atomicAdd(&cnt[i2], 1);
    }
    __syncthreads();
    if (tid < E_ && cnt[tid]) atomicAdd(&g_counts[tid], cnt[tid]);
}

// ---------------- combine (standalone, proven) ----------------
__global__ __launch_bounds__(256)
void combine_kernel(const float* __restrict__ preds_arg, float* __restrict__ combined) {
    const float* preds = preds_arg ? preds_arg : g_preds;
    const int warp = threadIdx.x >> 5, lane = threadIdx.x & 31;
    const int row = blockIdx.x * 8 + warp;
    const int packed = g_top2[row];
    const int e1 = packed & 0xFF, e2 = (packed >> 8) & 0xFF;
    const float* p1 = preds + ((size_t)e1 * B_ + row) * C_;
    const float* p2 = preds + ((size_t)e2 * B_ + row) * C_;
    float v1[4], v2[4];
#pragma unroll
    for (int i = 0; i < 4; i++) {
        int c = lane + i * 32;
        bool ok = c < C_;
        v1[i] = ok ? p1[c] : -3.4e38f;
        v2[i] = ok ? p2[c] : -3.4e38f;
    }
    float m1 = fmaxf(fmaxf(v1[0], v1[1]), fmaxf(v1[2], v1[3]));
    float m2 = fmaxf(fmaxf(v2[0], v2[1]), fmaxf(v2[2], v2[3]));
#pragma unroll
    for (int off = 16; off; off >>= 1) {
        m1 = fmaxf(m1, __shfl_xor_sync(0xffffffffu, m1, off));
        m2 = fmaxf(m2, __shfl_xor_sync(0xffffffffu, m2, off));
    }
    float s1 = 0.f, s2 = 0.f;
#pragma unroll
    for (int i = 0; i < 4; i++) {
        int c = lane + i * 32;
        v1[i] = (c < C_) ? expf(v1[i] - m1) : 0.f;
        v2[i] = (c < C_) ? expf(v2[i] - m2) : 0.f;
        s1 += v1[i]; s2 += v2[i];
    }
#pragma unroll
    for (int off = 16; off; off >>= 1) {
        s1 += __shfl_xor_sync(0xffffffffu, s1, off);
        s2 += __shfl_xor_sync(0xffffffffu, s2, off);
    }
    const float r1 = 0.5f / s1, r2 = 0.5f / s2;
    float* outr = combined + (size_t)row * C_;
#pragma unroll
    for (int i = 0; i < 4; i++) {
        int c = lane + i * 32;
        if (c < C_) outr[c] = v1[i] * r1 + v2[i] * r2;
    }
}

__global__ void zero_counts_kernel() { if (threadIdx.x < E_) g_counts[threadIdx.x] = 0; }
__global__ void write_counts_kernel(float* __restrict__ dst) {
    if (threadIdx.x < E_) dst[threadIdx.x] = (float)g_counts[threadIdx.x];
}

// ---------------------------------------------------------------------------
extern "C" void kernel_launch(void* const* d_in, const int* in_sizes, int n_in,
                              void* d_out, int out_size) {
    const float* x  = (const float*)d_in[0];
    const float* W1 = (const float*)d_in[1];
    const float* b1 = (const float*)d_in[2];
    const float* W2 = (const float*)d_in[3];
    const float* b2 = (const float*)d_in[4];
    const float* Wg = (const float*)d_in[5];
    float* out = (float*)d_out;

    const size_t n_combined = (size_t)B_ * C_;
    const size_t n_preds    = (size_t)E_ * B_ * C_;
    const bool has_preds  = (size_t)out_size >= n_combined + n_preds;
    const bool has_counts = (size_t)out_size >= n_combined + n_preds + E_;
    float* combined  = out;
    float* preds_out = has_preds ? out + n_combined : nullptr;

    zero_counts_kernel<<<1, 32>>>();
    prep_w1t<<<256, 256>>>(W1);
    prep_w2<<<128, 256>>>(W2);
    prep_x<<<8192, 256>>>(x);
    gate_kernel<<<B_ / 8, 256>>>(x, Wg);

    cudaFuncSetAttribute(fused_moe, cudaFuncAttributeMaxDynamicSharedMemorySize, SMEM_TOT);
    fused_moe<<<dim3(B_ / 64, E_), 128, SMEM_TOT>>>(b1, b2, preds_out);

    combine_kernel<<<B_ / 8, 256>>>(preds_out, combined);
    if (has_counts) write_counts_kernel<<<1, 32>>>(out + n_combined + n_preds);
}